// round 16
// baseline (speedup 1.0000x reference)
#include <cuda_runtime.h>
#include <math.h>

#define Bn 2
#define C 32
#define H 256
#define W 512
#define LH 64
#define LW 128
#define N_HP (Bn * H * W)      // 262144 hr pixels
#define N_P  (Bn * LH * LW)    // 16384 lr pixels

#define STR 36   // activation row stride (floats): 144B, 16B-aligned, bank-rotating

// packed f32x2 helpers (Blackwell sm_103a)
#define FMA2(d, a, b, c) \
    asm("fma.rn.f32x2 %0, %1, %2, %3;" : "=l"(d) : "l"(a), "l"(b), "l"(c))
#define PACK2(d, lo, hi) \
    asm("mov.b64 %0, {%1, %2};" : "=l"(d) : "f"(lo), "f"(hi))
#define UNPACK2(lo, hi, s) \
    asm("mov.b64 {%0, %1}, %2;" : "=f"(lo), "=f"(hi) : "l"(s))

// ONE constant block (used by k_main only):
// [0:512) W1 | [512:640) W2 | [640:648) W3
#define CW_TOTAL 648
__constant__ float cWB[CW_TOTAL];
#define cW1   (cWB)
#define cW2   (cWB + 512)
#define cW3   (cWB + 640)

__device__ float g_stage[CW_TOTAL];
__device__ float g_DT[9 * 16 * 32];           // dt[k][py*4+px][o]
__device__ float g_P[N_P * 32];               // W0_lr @ lr  per lr pixel
__device__ float g_HP[(size_t)N_HP * 32];     // W0_hr @ hr  per hr pixel (32 MB)

// ---------------------------------------------------------------------------
// Projection + prep, fused.
// Pixel blocks: stage W0 transposed in shared via COALESCED linear loads
// (scatter on the store side), then project hr/lr pixels.
// Last block: transpose W1/W2/W3 into g_stage, build full dt table.
// ---------------------------------------------------------------------------
__global__ __launch_bounds__(256) void k_proj(
    const float* __restrict__ hr, const float* __restrict__ lr,
    const float* __restrict__ w0, const float* __restrict__ w1,
    const float* __restrict__ w2, const float* __restrict__ w3)
{
    const int tid = threadIdx.x;

    // ---- prep block (last block): staging + dt table ----
    if (blockIdx.x == gridDim.x - 1) {
        for (int i = tid; i < 512; i += 256) {
            int c = i >> 4, j = i & 15;
            g_stage[c * 16 + j] = w1[j * 32 + c];
        }
        for (int i = tid; i < 128; i += 256) {
            int c = i >> 3, j = i & 7;
            g_stage[512 + c * 8 + j] = w2[j * 16 + c];
        }
        if (tid < 8) g_stage[640 + tid] = w3[tid];

        for (int i = tid; i < 9 * 16 * 32; i += 256) {
            int o  = i & 31;
            int px = (i >> 5) & 3;
            int py = (i >> 7) & 3;
            int k  = i >> 9;
            float bxf = (px < 2) ? (float)(px - 2) : (float)(px - 1);
            float byf = (py < 2) ? (float)(py - 2) : (float)(py - 1);
            float d0, d1;
            if (k == 0)                { d0 = bxf;              d1 = byf;              }
            else if (k == 1 || k == 5) { d0 = 4.f - (float)px;  d1 = byf;              }
            else if (k == 2 || k == 6) { d0 = (float)px + 1.f;  d1 = byf;              }
            else if (k == 3 || k == 7) { d0 = bxf;              d1 = 4.f - (float)py;  }
            else                       { d0 = bxf;              d1 = (float)py + 1.f;  }
            g_DT[i] = w0[o * 66 + 64] * d0 + w0[o * 66 + 65] * d1;
        }
        return;
    }

    // ---- pixel blocks: stage transposed W0 via coalesced linear loads ----
    __shared__ __align__(16) float sWh[32 * 32];   // W0hr [c][o]
    __shared__ __align__(16) float sWl[32 * 32];   // W0lr [c][o]
    for (int i = tid; i < 66 * 32; i += 256) {     // linear, coalesced
        float v = w0[i];
        int o = i / 66;
        int c = i - o * 66;
        if (c < 32)       sWl[c * 32 + o]        = v;
        else if (c < 64)  sWh[(c - 32) * 32 + o] = v;
        // c = 64, 65 (distance weights) unused here
    }
    __syncthreads();

    int i = blockIdx.x * 256 + tid;
    unsigned long long acc[16];
#pragma unroll
    for (int q = 0; q < 16; q++) acc[q] = 0ULL;

    if (i < N_HP) {
        int b   = i / (H * W);
        int rem = i - b * (H * W);
        const float* src = hr + (size_t)b * C * H * W + rem;
#pragma unroll 4
        for (int c = 0; c < 32; c++) {
            float v = src[(size_t)c * H * W];
            unsigned long long vv;
            PACK2(vv, v, v);
            const ulonglong2* wp = (const ulonglong2*)&sWh[c * 32];
#pragma unroll
            for (int q = 0; q < 8; q++) {
                ulonglong2 wv = wp[q];
                FMA2(acc[q * 2 + 0], vv, wv.x, acc[q * 2 + 0]);
                FMA2(acc[q * 2 + 1], vv, wv.y, acc[q * 2 + 1]);
            }
        }
        ulonglong2* dst = (ulonglong2*)&g_HP[(size_t)i * 32];
#pragma unroll
        for (int q = 0; q < 8; q++)
            dst[q] = make_ulonglong2(acc[q * 2], acc[q * 2 + 1]);
    } else {
        int j = i - N_HP;
        if (j >= N_P) return;
        int b   = j / (LH * LW);
        int rem = j - b * (LH * LW);
        const float* src = lr + (size_t)b * C * LH * LW + rem;
#pragma unroll 4
        for (int c = 0; c < 32; c++) {
            float v = src[c * (LH * LW)];
            unsigned long long vv;
            PACK2(vv, v, v);
            const ulonglong2* wp = (const ulonglong2*)&sWl[c * 32];
#pragma unroll
            for (int q = 0; q < 8; q++) {
                ulonglong2 wv = wp[q];
                FMA2(acc[q * 2 + 0], vv, wv.x, acc[q * 2 + 0]);
                FMA2(acc[q * 2 + 1], vv, wv.y, acc[q * 2 + 1]);
            }
        }
        ulonglong2* dst = (ulonglong2*)&g_P[(size_t)j * 32];
#pragma unroll
        for (int q = 0; q < 8; q++)
            dst[q] = make_ulonglong2(acc[q * 2], acc[q * 2 + 1]);
    }
}

// ---------------------------------------------------------------------------
// Main kernel (unchanged winning structure: one row per block, grid 4096).
// Block = 64-pixel strip x 9 directions; 288 threads = 9 warps;
// warp k = direction k; lane handles pixels lane, lane+32.
// ---------------------------------------------------------------------------
__global__ __launch_bounds__(288, 3) void k_main(float* __restrict__ out)
{
    __shared__ __align__(16) float sHP[64 * STR];    // hpart [pix][o]
    __shared__ __align__(16) float sP[54 * STR];     // P halo [3x18 cells][o]
    __shared__ __align__(16) float sDT[36 * STR];    // dt [k*4+px][o]
    __shared__ float sL[9 * 64];                     // logits [k][pix]

    const int tid = threadIdx.x;
    const int x0  = blockIdx.x * 64;
    const int y   = blockIdx.y;
    const int b   = blockIdx.z;
    const int py  = y & 3;
    const int ly0 = y >> 2;
    const int lx0 = x0 >> 2;

    // ---- prologue: three copy loops, one sync ----
    {
        const float* hp_src = g_HP + (((size_t)b * H + y) * W + x0) * 32;
        for (int i = tid; i < 512; i += 288) {
            int pix = i >> 3;
            int og  = (i & 7) << 2;
            *(float4*)&sHP[pix * STR + og] = *(const float4*)&hp_src[pix * 32 + og];
        }
        for (int i = tid; i < 54 * 8; i += 288) {
            int cell = i >> 3;
            int og   = (i & 7) << 2;
            int lxl  = cell % 18, lyl = cell / 18;
            int glx  = min(max(lx0 - 1 + lxl, 0), LW - 1);
            int gly  = min(max(ly0 - 1 + lyl, 0), LH - 1);
            *(float4*)&sP[cell * STR + og] =
                *(const float4*)&g_P[(((size_t)b * LH + gly) * LW + glx) * 32 + og];
        }
        for (int i = tid; i < 9 * 4 * 8; i += 288) {
            int og = (i & 7) << 2;
            int px = (i >> 3) & 3;
            int kk = i >> 5;
            *(float4*)&sDT[(kk * 4 + px) * STR + og] =
                *(const float4*)&g_DT[((kk * 16 + py * 4 + px) << 5) + og];
        }
    }
    __syncthreads();

    // ---- MLP: warp k = direction k; lane does pixels lane, lane+32 ----
    {
        const int k    = tid >> 5;          // 0..8
        const int lane = tid & 31;
        const int pA   = lane;
        const int pB   = lane + 32;
        const int px   = pA & 3;

        // dir offsets: dy=-1 k in {3,5,6}, dy=+1 {4,7,8}; dx=-1 {1,5,7}, dx=+1 {2,6,8}
        const unsigned NY = (1u<<3)|(1u<<5)|(1u<<6), PY = (1u<<4)|(1u<<7)|(1u<<8);
        const unsigned NX = (1u<<1)|(1u<<5)|(1u<<7), PX = (1u<<2)|(1u<<6)|(1u<<8);
        int dy = (int)((PY >> k) & 1u) - (int)((NY >> k) & 1u);
        int dx = (int)((PX >> k) & 1u) - (int)((NX >> k) & 1u);
        int yn = y + dy * 4;
        bool vy = (yn >= 0) & (yn < H);
        int xnA = x0 + pA + dx * 4;
        int xnB = x0 + pB + dx * 4;
        bool validA = vy & (xnA >= 0) & (xnA < W);
        bool validB = vy & (xnB >= 0) & (xnB < W);

        const float* hpA = &sHP[pA * STR];
        const float* hpB = &sHP[pB * STR];
        const float* prA = &sP[((1 + dy) * 18 + (pA >> 2) + 1 + dx) * STR];
        const float* prB = prA + 8 * STR;
        const float* dtr = &sDT[(k * 4 + px) * STR];

        unsigned long long h1A[8], h1B[8];
#pragma unroll
        for (int j = 0; j < 8; j++) { h1A[j] = 0ULL; h1B[j] = 0ULL; }

#pragma unroll 2
        for (int c4 = 0; c4 < 32; c4 += 4) {
            const float4 hA4 = *(const float4*)&hpA[c4];
            const float4 hB4 = *(const float4*)&hpB[c4];
            const float4 pA4 = *(const float4*)&prA[c4];
            const float4 pB4 = *(const float4*)&prB[c4];
            const float4 dt4 = *(const float4*)&dtr[c4];

            float aA[4], aB[4];
            {
                float t;
                t = hA4.x + pA4.x + dt4.x; aA[0] = fmaxf(t, 0.01f * t);
                t = hA4.y + pA4.y + dt4.y; aA[1] = fmaxf(t, 0.01f * t);
                t = hA4.z + pA4.z + dt4.z; aA[2] = fmaxf(t, 0.01f * t);
                t = hA4.w + pA4.w + dt4.w; aA[3] = fmaxf(t, 0.01f * t);
                t = hB4.x + pB4.x + dt4.x; aB[0] = fmaxf(t, 0.01f * t);
                t = hB4.y + pB4.y + dt4.y; aB[1] = fmaxf(t, 0.01f * t);
                t = hB4.z + pB4.z + dt4.z; aB[2] = fmaxf(t, 0.01f * t);
                t = hB4.w + pB4.w + dt4.w; aB[3] = fmaxf(t, 0.01f * t);
            }
#pragma unroll
            for (int cc = 0; cc < 4; cc++) {
                const int c = c4 + cc;
                const ulonglong2* wp = (const ulonglong2*)&cW1[c * 16];
                unsigned long long apA, apB;
                PACK2(apA, aA[cc], aA[cc]);
                PACK2(apB, aB[cc], aB[cc]);
#pragma unroll
                for (int q = 0; q < 4; q++) {
                    ulonglong2 wv = wp[q];
                    FMA2(h1A[q * 2 + 0], apA, wv.x, h1A[q * 2 + 0]);
                    FMA2(h1A[q * 2 + 1], apA, wv.y, h1A[q * 2 + 1]);
                    FMA2(h1B[q * 2 + 0], apB, wv.x, h1B[q * 2 + 0]);
                    FMA2(h1B[q * 2 + 1], apB, wv.y, h1B[q * 2 + 1]);
                }
            }
        }

        unsigned long long h2A[4], h2B[4];
#pragma unroll
        for (int j = 0; j < 4; j++) { h2A[j] = 0ULL; h2B[j] = 0ULL; }
#pragma unroll 2
        for (int c2 = 0; c2 < 8; c2++) {
            float uA0, uA1, uB0, uB1;
            UNPACK2(uA0, uA1, h1A[c2]);
            UNPACK2(uB0, uB1, h1B[c2]);
            uA0 = fmaxf(uA0, 0.01f * uA0);  uA1 = fmaxf(uA1, 0.01f * uA1);
            uB0 = fmaxf(uB0, 0.01f * uB0);  uB1 = fmaxf(uB1, 0.01f * uB1);
            unsigned long long aA0, aA1, aB0, aB1;
            PACK2(aA0, uA0, uA0); PACK2(aA1, uA1, uA1);
            PACK2(aB0, uB0, uB0); PACK2(aB1, uB1, uB1);

            const ulonglong2* wp0 = (const ulonglong2*)&cW2[(2 * c2) * 8];
            const ulonglong2* wp1 = (const ulonglong2*)&cW2[(2 * c2 + 1) * 8];
            ulonglong2 w0v = wp0[0], w0w = wp0[1];
            ulonglong2 w1v = wp1[0], w1w = wp1[1];
            FMA2(h2A[0], aA0, w0v.x, h2A[0]); FMA2(h2A[1], aA0, w0v.y, h2A[1]);
            FMA2(h2A[2], aA0, w0w.x, h2A[2]); FMA2(h2A[3], aA0, w0w.y, h2A[3]);
            FMA2(h2A[0], aA1, w1v.x, h2A[0]); FMA2(h2A[1], aA1, w1v.y, h2A[1]);
            FMA2(h2A[2], aA1, w1w.x, h2A[2]); FMA2(h2A[3], aA1, w1w.y, h2A[3]);
            FMA2(h2B[0], aB0, w0v.x, h2B[0]); FMA2(h2B[1], aB0, w0v.y, h2B[1]);
            FMA2(h2B[2], aB0, w0w.x, h2B[2]); FMA2(h2B[3], aB0, w0w.y, h2B[3]);
            FMA2(h2B[0], aB1, w1v.x, h2B[0]); FMA2(h2B[1], aB1, w1v.y, h2B[1]);
            FMA2(h2B[2], aB1, w1w.x, h2B[2]); FMA2(h2B[3], aB1, w1w.y, h2B[3]);
        }

        float logitA = 0.f, logitB = 0.f;
#pragma unroll
        for (int j = 0; j < 4; j++) {
            float vA0, vA1, vB0, vB1;
            UNPACK2(vA0, vA1, h2A[j]);
            UNPACK2(vB0, vB1, h2B[j]);
            float w30 = cW3[2 * j], w31 = cW3[2 * j + 1];
            logitA = fmaf(fmaxf(vA0, 0.01f * vA0), w30, logitA);
            logitA = fmaf(fmaxf(vA1, 0.01f * vA1), w31, logitA);
            logitB = fmaf(fmaxf(vB0, 0.01f * vB0), w30, logitB);
            logitB = fmaf(fmaxf(vB1, 0.01f * vB1), w31, logitB);
        }

        sL[k * 64 + pA] = validA ? logitA : -100.0f;
        sL[k * 64 + pB] = validB ? logitB : -100.0f;
    }
    __syncthreads();

    // ---- softmax over 9 dirs, write out ----
    if (tid < 64) {
        float v[9], m = -1e30f;
#pragma unroll
        for (int k = 0; k < 9; k++) {
            v[k] = sL[k * 64 + tid];
            m = fmaxf(m, v[k]);
        }
        float s = 0.f;
#pragma unroll
        for (int k = 0; k < 9; k++) {
            v[k] = __expf(v[k] - m);
            s += v[k];
        }
        float inv = 1.f / s;
        float* op = out + (((size_t)b * 9) * H + y) * W + x0 + tid;
#pragma unroll
        for (int k = 0; k < 9; k++)
            op[(size_t)k * H * W] = v[k] * inv;
    }
}

// ---------------------------------------------------------------------------
extern "C" void kernel_launch(void* const* d_in, const int* in_sizes, int n_in,
                              void* d_out, int out_size)
{
    const float* lr = (const float*)d_in[0];
    const float* hr = (const float*)d_in[1];
    // d_in[2], d_in[3] (lr_feature_r / hr_feature_r) unused by the reference
    const float* w0 = (const float*)d_in[4];
    const float* w1 = (const float*)d_in[5];
    const float* w2 = (const float*)d_in[6];
    const float* w3 = (const float*)d_in[7];
    float* out = (float*)d_out;

    // k_proj also does the prep work (last block); then one memcpy to const.
    int nblk = (N_HP + N_P + 255) / 256 + 1;
    k_proj<<<nblk, 256>>>(hr, lr, w0, w1, w2, w3);

    void* stage_ptr = nullptr;
    cudaGetSymbolAddress(&stage_ptr, g_stage);
    cudaMemcpyToSymbolAsync(cWB, stage_ptr, CW_TOTAL * sizeof(float), 0,
                            cudaMemcpyDeviceToDevice, 0);

    dim3 grid(W / 64, H, Bn);
    k_main<<<grid, 288>>>(out);
}

// round 17
// speedup vs baseline: 1.0878x; 1.0878x over previous
#include <cuda_runtime.h>
#include <math.h>

#define Bn 2
#define C 32
#define H 256
#define W 512
#define LH 64
#define LW 128
#define N_HP (Bn * H * W)      // 262144 hr pixels
#define N_P  (Bn * LH * LW)    // 16384 lr pixels

#define STR 36   // activation row stride (floats): 144B, 16B-aligned, bank-rotating

// packed f32x2 helpers (Blackwell sm_103a)
#define FMA2(d, a, b, c) \
    asm("fma.rn.f32x2 %0, %1, %2, %3;" : "=l"(d) : "l"(a), "l"(b), "l"(c))
#define PACK2(d, lo, hi) \
    asm("mov.b64 %0, {%1, %2};" : "=l"(d) : "f"(lo), "f"(hi))
#define UNPACK2(lo, hi, s) \
    asm("mov.b64 {%0, %1}, %2;" : "=f"(lo), "=f"(hi) : "l"(s))

// ONE constant block: [0:1024) W0hr | [1024:2048) W0lr | [2048:2560) W1
//                     [2560:2688) W2 | [2688:2696) W3
#define CW_TOTAL 2696
__constant__ float cWB[CW_TOTAL];
#define cW0hr (cWB)
#define cW0lr (cWB + 1024)
#define cW1   (cWB + 2048)
#define cW2   (cWB + 2560)
#define cW3   (cWB + 2688)

__device__ float g_stage[CW_TOTAL];
__device__ float g_DT[9 * 16 * 32];           // dt[k][py*4+px][o]
__device__ float g_P[N_P * 32];               // W0_lr @ lr  per lr pixel
__device__ float g_HP[(size_t)N_HP * 32];     // W0_hr @ hr  per hr pixel (32 MB)

// ---------------------------------------------------------------------------
// Prep: transpose all weights into one staging buffer; build full dt table.
// ---------------------------------------------------------------------------
__global__ void k_prep(const float* __restrict__ w0,
                       const float* __restrict__ w1,
                       const float* __restrict__ w2,
                       const float* __restrict__ w3)
{
    int t = blockIdx.x * blockDim.x + threadIdx.x;
    int nt = gridDim.x * blockDim.x;
    for (int i = t; i < 1024; i += nt) {
        int c = i >> 5, o = i & 31;
        g_stage[i]        = w0[o * 66 + 32 + c];   // W0hr [c][o]
        g_stage[1024 + i] = w0[o * 66 + c];        // W0lr [c][o]
    }
    for (int i = t; i < 512; i += nt) {
        int c = i >> 4, j = i & 15;
        g_stage[2048 + c * 16 + j] = w1[j * 32 + c];
    }
    for (int i = t; i < 128; i += nt) {
        int c = i >> 3, j = i & 7;
        g_stage[2560 + c * 8 + j] = w2[j * 16 + c];
    }
    for (int i = t; i < 8; i += nt) g_stage[2688 + i] = w3[i];

    for (int i = t; i < 9 * 16 * 32; i += nt) {
        int o  = i & 31;
        int px = (i >> 5) & 3;
        int py = (i >> 7) & 3;
        int k  = i >> 9;
        float bxf = (px < 2) ? (float)(px - 2) : (float)(px - 1);
        float byf = (py < 2) ? (float)(py - 2) : (float)(py - 1);
        float d0, d1;
        if (k == 0)                { d0 = bxf;              d1 = byf;              }
        else if (k == 1 || k == 5) { d0 = 4.f - (float)px;  d1 = byf;              }
        else if (k == 2 || k == 6) { d0 = (float)px + 1.f;  d1 = byf;              }
        else if (k == 3 || k == 7) { d0 = bxf;              d1 = 4.f - (float)py;  }
        else                       { d0 = bxf;              d1 = (float)py + 1.f;  }
        g_DT[i] = w0[o * 66 + 64] * d0 + w0[o * 66 + 65] * d1;
    }
}

// ---------------------------------------------------------------------------
// Projection: g_HP[i][o] = W0_hr @ hr(pixel i);  g_P[j][o] = W0_lr @ lr(pixel j)
// ---------------------------------------------------------------------------
__global__ __launch_bounds__(256) void k_proj(
    const float* __restrict__ hr, const float* __restrict__ lr)
{
    int i = blockIdx.x * 256 + threadIdx.x;
    unsigned long long acc[16];
#pragma unroll
    for (int q = 0; q < 16; q++) acc[q] = 0ULL;

    if (i < N_HP) {
        int b   = i / (H * W);
        int rem = i - b * (H * W);
        const float* src = hr + (size_t)b * C * H * W + rem;
#pragma unroll 4
        for (int c = 0; c < 32; c++) {
            float v = src[(size_t)c * H * W];
            unsigned long long vv;
            PACK2(vv, v, v);
            const ulonglong2* wp = (const ulonglong2*)&cW0hr[c * 32];
#pragma unroll
            for (int q = 0; q < 8; q++) {
                ulonglong2 wv = wp[q];
                FMA2(acc[q * 2 + 0], vv, wv.x, acc[q * 2 + 0]);
                FMA2(acc[q * 2 + 1], vv, wv.y, acc[q * 2 + 1]);
            }
        }
        ulonglong2* dst = (ulonglong2*)&g_HP[(size_t)i * 32];
#pragma unroll
        for (int q = 0; q < 8; q++)
            dst[q] = make_ulonglong2(acc[q * 2], acc[q * 2 + 1]);
    } else {
        int j = i - N_HP;
        if (j >= N_P) return;
        int b   = j / (LH * LW);
        int rem = j - b * (LH * LW);
        const float* src = lr + (size_t)b * C * LH * LW + rem;
#pragma unroll 4
        for (int c = 0; c < 32; c++) {
            float v = src[c * (LH * LW)];
            unsigned long long vv;
            PACK2(vv, v, v);
            const ulonglong2* wp = (const ulonglong2*)&cW0lr[c * 32];
#pragma unroll
            for (int q = 0; q < 8; q++) {
                ulonglong2 wv = wp[q];
                FMA2(acc[q * 2 + 0], vv, wv.x, acc[q * 2 + 0]);
                FMA2(acc[q * 2 + 1], vv, wv.y, acc[q * 2 + 1]);
            }
        }
        ulonglong2* dst = (ulonglong2*)&g_P[(size_t)j * 32];
#pragma unroll
        for (int q = 0; q < 8; q++)
            dst[q] = make_ulonglong2(acc[q * 2], acc[q * 2 + 1]);
    }
}

// ---------------------------------------------------------------------------
// Main kernel: one row per block, grid 4096; 288 threads = 9 warps;
// warp k = direction k; lane handles pixels lane, lane+32.
// __launch_bounds__(288, 4): cap 56 regs -> 4 CTAs/SM (36 warps) experiment.
// ---------------------------------------------------------------------------
__global__ __launch_bounds__(288, 4) void k_main(float* __restrict__ out)
{
    __shared__ __align__(16) float sHP[64 * STR];    // hpart [pix][o]
    __shared__ __align__(16) float sP[54 * STR];     // P halo [3x18 cells][o]
    __shared__ __align__(16) float sDT[36 * STR];    // dt [k*4+px][o]
    __shared__ float sL[9 * 64];                     // logits [k][pix]

    const int tid = threadIdx.x;
    const int x0  = blockIdx.x * 64;
    const int y   = blockIdx.y;
    const int b   = blockIdx.z;
    const int py  = y & 3;
    const int ly0 = y >> 2;
    const int lx0 = x0 >> 2;

    // ---- prologue: three copy loops, one sync ----
    {
        const float* hp_src = g_HP + (((size_t)b * H + y) * W + x0) * 32;
        for (int i = tid; i < 512; i += 288) {
            int pix = i >> 3;
            int og  = (i & 7) << 2;
            *(float4*)&sHP[pix * STR + og] = *(const float4*)&hp_src[pix * 32 + og];
        }
        for (int i = tid; i < 54 * 8; i += 288) {
            int cell = i >> 3;
            int og   = (i & 7) << 2;
            int lxl  = cell % 18, lyl = cell / 18;
            int glx  = min(max(lx0 - 1 + lxl, 0), LW - 1);
            int gly  = min(max(ly0 - 1 + lyl, 0), LH - 1);
            *(float4*)&sP[cell * STR + og] =
                *(const float4*)&g_P[(((size_t)b * LH + gly) * LW + glx) * 32 + og];
        }
        for (int i = tid; i < 9 * 4 * 8; i += 288) {
            int og = (i & 7) << 2;
            int px = (i >> 3) & 3;
            int kk = i >> 5;
            *(float4*)&sDT[(kk * 4 + px) * STR + og] =
                *(const float4*)&g_DT[((kk * 16 + py * 4 + px) << 5) + og];
        }
    }
    __syncthreads();

    // ---- MLP: warp k = direction k; lane does pixels lane, lane+32 ----
    {
        const int k    = tid >> 5;          // 0..8
        const int lane = tid & 31;
        const int pA   = lane;
        const int pB   = lane + 32;
        const int px   = pA & 3;

        // dir offsets: dy=-1 k in {3,5,6}, dy=+1 {4,7,8}; dx=-1 {1,5,7}, dx=+1 {2,6,8}
        const unsigned NY = (1u<<3)|(1u<<5)|(1u<<6), PY = (1u<<4)|(1u<<7)|(1u<<8);
        const unsigned NX = (1u<<1)|(1u<<5)|(1u<<7), PX = (1u<<2)|(1u<<6)|(1u<<8);
        int dy = (int)((PY >> k) & 1u) - (int)((NY >> k) & 1u);
        int dx = (int)((PX >> k) & 1u) - (int)((NX >> k) & 1u);
        int yn = y + dy * 4;
        bool vy = (yn >= 0) & (yn < H);
        int xnA = x0 + pA + dx * 4;
        int xnB = x0 + pB + dx * 4;
        bool validA = vy & (xnA >= 0) & (xnA < W);
        bool validB = vy & (xnB >= 0) & (xnB < W);

        const float* hpA = &sHP[pA * STR];
        const float* hpB = &sHP[pB * STR];
        const float* prA = &sP[((1 + dy) * 18 + (pA >> 2) + 1 + dx) * STR];
        const float* prB = prA + 8 * STR;
        const float* dtr = &sDT[(k * 4 + px) * STR];

        unsigned long long h1A[8], h1B[8];
#pragma unroll
        for (int j = 0; j < 8; j++) { h1A[j] = 0ULL; h1B[j] = 0ULL; }

#pragma unroll 2
        for (int c4 = 0; c4 < 32; c4 += 4) {
            const float4 hA4 = *(const float4*)&hpA[c4];
            const float4 hB4 = *(const float4*)&hpB[c4];
            const float4 pA4 = *(const float4*)&prA[c4];
            const float4 pB4 = *(const float4*)&prB[c4];
            const float4 dt4 = *(const float4*)&dtr[c4];

            float aA[4], aB[4];
            {
                float t;
                t = hA4.x + pA4.x + dt4.x; aA[0] = fmaxf(t, 0.01f * t);
                t = hA4.y + pA4.y + dt4.y; aA[1] = fmaxf(t, 0.01f * t);
                t = hA4.z + pA4.z + dt4.z; aA[2] = fmaxf(t, 0.01f * t);
                t = hA4.w + pA4.w + dt4.w; aA[3] = fmaxf(t, 0.01f * t);
                t = hB4.x + pB4.x + dt4.x; aB[0] = fmaxf(t, 0.01f * t);
                t = hB4.y + pB4.y + dt4.y; aB[1] = fmaxf(t, 0.01f * t);
                t = hB4.z + pB4.z + dt4.z; aB[2] = fmaxf(t, 0.01f * t);
                t = hB4.w + pB4.w + dt4.w; aB[3] = fmaxf(t, 0.01f * t);
            }
#pragma unroll
            for (int cc = 0; cc < 4; cc++) {
                const int c = c4 + cc;
                const ulonglong2* wp = (const ulonglong2*)&cW1[c * 16];
                unsigned long long apA, apB;
                PACK2(apA, aA[cc], aA[cc]);
                PACK2(apB, aB[cc], aB[cc]);
#pragma unroll
                for (int q = 0; q < 4; q++) {
                    ulonglong2 wv = wp[q];
                    FMA2(h1A[q * 2 + 0], apA, wv.x, h1A[q * 2 + 0]);
                    FMA2(h1A[q * 2 + 1], apA, wv.y, h1A[q * 2 + 1]);
                    FMA2(h1B[q * 2 + 0], apB, wv.x, h1B[q * 2 + 0]);
                    FMA2(h1B[q * 2 + 1], apB, wv.y, h1B[q * 2 + 1]);
                }
            }
        }

        unsigned long long h2A[4], h2B[4];
#pragma unroll
        for (int j = 0; j < 4; j++) { h2A[j] = 0ULL; h2B[j] = 0ULL; }
#pragma unroll 2
        for (int c2 = 0; c2 < 8; c2++) {
            float uA0, uA1, uB0, uB1;
            UNPACK2(uA0, uA1, h1A[c2]);
            UNPACK2(uB0, uB1, h1B[c2]);
            uA0 = fmaxf(uA0, 0.01f * uA0);  uA1 = fmaxf(uA1, 0.01f * uA1);
            uB0 = fmaxf(uB0, 0.01f * uB0);  uB1 = fmaxf(uB1, 0.01f * uB1);
            unsigned long long aA0, aA1, aB0, aB1;
            PACK2(aA0, uA0, uA0); PACK2(aA1, uA1, uA1);
            PACK2(aB0, uB0, uB0); PACK2(aB1, uB1, uB1);

            const ulonglong2* wp0 = (const ulonglong2*)&cW2[(2 * c2) * 8];
            const ulonglong2* wp1 = (const ulonglong2*)&cW2[(2 * c2 + 1) * 8];
            ulonglong2 w0v = wp0[0], w0w = wp0[1];
            ulonglong2 w1v = wp1[0], w1w = wp1[1];
            FMA2(h2A[0], aA0, w0v.x, h2A[0]); FMA2(h2A[1], aA0, w0v.y, h2A[1]);
            FMA2(h2A[2], aA0, w0w.x, h2A[2]); FMA2(h2A[3], aA0, w0w.y, h2A[3]);
            FMA2(h2A[0], aA1, w1v.x, h2A[0]); FMA2(h2A[1], aA1, w1v.y, h2A[1]);
            FMA2(h2A[2], aA1, w1w.x, h2A[2]); FMA2(h2A[3], aA1, w1w.y, h2A[3]);
            FMA2(h2B[0], aB0, w0v.x, h2B[0]); FMA2(h2B[1], aB0, w0v.y, h2B[1]);
            FMA2(h2B[2], aB0, w0w.x, h2B[2]); FMA2(h2B[3], aB0, w0w.y, h2B[3]);
            FMA2(h2B[0], aB1, w1v.x, h2B[0]); FMA2(h2B[1], aB1, w1v.y, h2B[1]);
            FMA2(h2B[2], aB1, w1w.x, h2B[2]); FMA2(h2B[3], aB1, w1w.y, h2B[3]);
        }

        float logitA = 0.f, logitB = 0.f;
#pragma unroll
        for (int j = 0; j < 4; j++) {
            float vA0, vA1, vB0, vB1;
            UNPACK2(vA0, vA1, h2A[j]);
            UNPACK2(vB0, vB1, h2B[j]);
            float w30 = cW3[2 * j], w31 = cW3[2 * j + 1];
            logitA = fmaf(fmaxf(vA0, 0.01f * vA0), w30, logitA);
            logitA = fmaf(fmaxf(vA1, 0.01f * vA1), w31, logitA);
            logitB = fmaf(fmaxf(vB0, 0.01f * vB0), w30, logitB);
            logitB = fmaf(fmaxf(vB1, 0.01f * vB1), w31, logitB);
        }

        sL[k * 64 + pA] = validA ? logitA : -100.0f;
        sL[k * 64 + pB] = validB ? logitB : -100.0f;
    }
    __syncthreads();

    // ---- softmax over 9 dirs, write out ----
    if (tid < 64) {
        float v[9], m = -1e30f;
#pragma unroll
        for (int k = 0; k < 9; k++) {
            v[k] = sL[k * 64 + tid];
            m = fmaxf(m, v[k]);
        }
        float s = 0.f;
#pragma unroll
        for (int k = 0; k < 9; k++) {
            v[k] = __expf(v[k] - m);
            s += v[k];
        }
        float inv = 1.f / s;
        float* op = out + (((size_t)b * 9) * H + y) * W + x0 + tid;
#pragma unroll
        for (int k = 0; k < 9; k++)
            op[(size_t)k * H * W] = v[k] * inv;
    }
}

// ---------------------------------------------------------------------------
extern "C" void kernel_launch(void* const* d_in, const int* in_sizes, int n_in,
                              void* d_out, int out_size)
{
    const float* lr = (const float*)d_in[0];
    const float* hr = (const float*)d_in[1];
    // d_in[2], d_in[3] (lr_feature_r / hr_feature_r) unused by the reference
    const float* w0 = (const float*)d_in[4];
    const float* w1 = (const float*)d_in[5];
    const float* w2 = (const float*)d_in[6];
    const float* w3 = (const float*)d_in[7];
    float* out = (float*)d_out;

    k_prep<<<8, 256>>>(w0, w1, w2, w3);

    void* stage_ptr = nullptr;
    cudaGetSymbolAddress(&stage_ptr, g_stage);
    cudaMemcpyToSymbolAsync(cWB, stage_ptr, CW_TOTAL * sizeof(float), 0,
                            cudaMemcpyDeviceToDevice, 0);

    k_proj<<<(N_HP + N_P + 255) / 256, 256>>>(hr, lr);

    dim3 grid(W / 64, H, Bn);
    k_main<<<grid, 288>>>(out);
}